// round 1
// baseline (speedup 1.0000x reference)
#include <cuda_runtime.h>
#include <cuda_bf16.h>
#include <stdint.h>

// Problem constants (match reference)
#define INPUT_DIM  1024
#define LATENT_DIM 256
#define NUM_EMB    8192
#define BATCH      8192

// Scratch: allocation-free __device__ globals
__device__ float              g_inv_norm[NUM_EMB];
__device__ unsigned long long g_keys[BATCH];

// Tiling config
constexpr int BM = 128, BN = 128, BK = 16, TM = 8, TN = 8;
constexpr int BMP = 132;            // padded leading dim for smem tiles (2-way max conflict)
constexpr int NTHREADS = (BM / TM) * (BN / TN); // 256

// ---------------------------------------------------------------------------
// init: codebook inverse norms + reset argmax keys (runs every launch; cheap)
// ---------------------------------------------------------------------------
__global__ void init_kernel(const float* __restrict__ emb) {
    int i = blockIdx.x * blockDim.x + threadIdx.x;
    if (i < NUM_EMB) {
        const float4* p = reinterpret_cast<const float4*>(emb + (size_t)i * LATENT_DIM);
        float s = 0.0f;
        #pragma unroll 8
        for (int j = 0; j < LATENT_DIM / 4; j++) {
            float4 v = p[j];
            s += v.x * v.x + v.y * v.y + v.z * v.z + v.w * v.w;
        }
        g_inv_norm[i] = 1.0f / sqrtf(s);
    }
    if (i < BATCH) g_keys[i] = 0ull;
}

// ---------------------------------------------------------------------------
// Shared tile loader: 128 rows x 16 K, transposed into smem [BK][BMP].
// src is row-major [rows, ld] with K contiguous (both A and B^T operands).
// ---------------------------------------------------------------------------
__device__ __forceinline__ void load_tile(const float* __restrict__ src, int ld,
                                          int row0, int k0,
                                          float* __restrict__ dst, int tid) {
    #pragma unroll
    for (int it = 0; it < 2; it++) {
        int idx = tid + it * NTHREADS;       // 0..511
        int r   = idx >> 2;                  // 0..127
        int kq  = (idx & 3) * 4;             // 0,4,8,12
        float4 v = *reinterpret_cast<const float4*>(
            &src[(size_t)(row0 + r) * ld + k0 + kq]);
        dst[(kq + 0) * BMP + r] = v.x;
        dst[(kq + 1) * BMP + r] = v.y;
        dst[(kq + 2) * BMP + r] = v.z;
        dst[(kq + 3) * BMP + r] = v.w;
    }
}

// ---------------------------------------------------------------------------
// C[M,N] = A[M,K] @ B[N,K]^T + bias[N]   (fp32, 128x128x16, 8x8/thread)
// ---------------------------------------------------------------------------
__global__ void __launch_bounds__(NTHREADS)
sgemm_abT_bias(const float* __restrict__ A, const float* __restrict__ B,
               const float* __restrict__ bias, float* __restrict__ C,
               int M, int N, int K) {
    __shared__ __align__(16) float As[BK * BMP];
    __shared__ __align__(16) float Bs[BK * BMP];

    const int tid  = threadIdx.x;
    const int tx   = tid & 15;     // col group
    const int ty   = tid >> 4;     // row group
    const int row0 = blockIdx.y * BM;
    const int col0 = blockIdx.x * BN;

    float acc[TM][TN] = {};

    for (int k0 = 0; k0 < K; k0 += BK) {
        load_tile(A, K, row0, k0, As, tid);
        load_tile(B, K, col0, k0, Bs, tid);
        __syncthreads();
        #pragma unroll
        for (int kk = 0; kk < BK; kk++) {
            float rm[TM], rn[TN];
            float4 a0 = *reinterpret_cast<const float4*>(&As[kk * BMP + ty * TM]);
            float4 a1 = *reinterpret_cast<const float4*>(&As[kk * BMP + ty * TM + 4]);
            float4 b0 = *reinterpret_cast<const float4*>(&Bs[kk * BMP + tx * TN]);
            float4 b1 = *reinterpret_cast<const float4*>(&Bs[kk * BMP + tx * TN + 4]);
            rm[0]=a0.x; rm[1]=a0.y; rm[2]=a0.z; rm[3]=a0.w;
            rm[4]=a1.x; rm[5]=a1.y; rm[6]=a1.z; rm[7]=a1.w;
            rn[0]=b0.x; rn[1]=b0.y; rn[2]=b0.z; rn[3]=b0.w;
            rn[4]=b1.x; rn[5]=b1.y; rn[6]=b1.z; rn[7]=b1.w;
            #pragma unroll
            for (int m = 0; m < TM; m++)
                #pragma unroll
                for (int n = 0; n < TN; n++)
                    acc[m][n] = fmaf(rm[m], rn[n], acc[m][n]);
        }
        __syncthreads();
    }

    #pragma unroll
    for (int m = 0; m < TM; m++) {
        int r = row0 + ty * TM + m;
        #pragma unroll
        for (int n = 0; n < TN; n += 4) {
            int c = col0 + tx * TN + n;
            float4 v;
            v.x = acc[m][n + 0] + bias[c + 0];
            v.y = acc[m][n + 1] + bias[c + 1];
            v.z = acc[m][n + 2] + bias[c + 2];
            v.w = acc[m][n + 3] + bias[c + 3];
            *reinterpret_cast<float4*>(&C[(size_t)r * N + c]) = v;
        }
    }
}

// ---------------------------------------------------------------------------
// Distance GEMM with fused argmax epilogue.
// scores[i,k] = (z_i . emb_k) * inv_norm[k]; running argmax per row via
// order-preserving packed u64 atomicMax (ties -> lowest index, like argmin).
// ---------------------------------------------------------------------------
__device__ __forceinline__ unsigned int float_key(float f) {
    unsigned int u = __float_as_uint(f);
    return (u & 0x80000000u) ? ~u : (u | 0x80000000u);
}

__global__ void __launch_bounds__(NTHREADS)
sgemm_argmax(const float* __restrict__ Z, const float* __restrict__ E,
             int M, int N, int K) {
    __shared__ __align__(16) float As[BK * BMP];
    __shared__ __align__(16) float Bs[BK * BMP];
    __shared__ unsigned long long red[BM * 16];

    const int tid  = threadIdx.x;
    const int tx   = tid & 15;
    const int ty   = tid >> 4;
    const int row0 = blockIdx.y * BM;
    const int col0 = blockIdx.x * BN;

    float acc[TM][TN] = {};

    for (int k0 = 0; k0 < K; k0 += BK) {
        load_tile(Z, K, row0, k0, As, tid);
        load_tile(E, K, col0, k0, Bs, tid);
        __syncthreads();
        #pragma unroll
        for (int kk = 0; kk < BK; kk++) {
            float rm[TM], rn[TN];
            float4 a0 = *reinterpret_cast<const float4*>(&As[kk * BMP + ty * TM]);
            float4 a1 = *reinterpret_cast<const float4*>(&As[kk * BMP + ty * TM + 4]);
            float4 b0 = *reinterpret_cast<const float4*>(&Bs[kk * BMP + tx * TN]);
            float4 b1 = *reinterpret_cast<const float4*>(&Bs[kk * BMP + tx * TN + 4]);
            rm[0]=a0.x; rm[1]=a0.y; rm[2]=a0.z; rm[3]=a0.w;
            rm[4]=a1.x; rm[5]=a1.y; rm[6]=a1.z; rm[7]=a1.w;
            rn[0]=b0.x; rn[1]=b0.y; rn[2]=b0.z; rn[3]=b0.w;
            rn[4]=b1.x; rn[5]=b1.y; rn[6]=b1.z; rn[7]=b1.w;
            #pragma unroll
            for (int m = 0; m < TM; m++)
                #pragma unroll
                for (int n = 0; n < TN; n++)
                    acc[m][n] = fmaf(rm[m], rn[n], acc[m][n]);
        }
        __syncthreads();
    }

    // per-thread best over its 8 columns, per row
    float inv[TN];
    #pragma unroll
    for (int n = 0; n < TN; n++) inv[n] = g_inv_norm[col0 + tx * TN + n];

    #pragma unroll
    for (int m = 0; m < TM; m++) {
        unsigned long long best = 0ull;
        #pragma unroll
        for (int n = 0; n < TN; n++) {
            int c = col0 + tx * TN + n;
            float s = acc[m][n] * inv[n];
            unsigned long long key =
                ((unsigned long long)float_key(s) << 32) |
                (unsigned long long)(0xFFFFFFFFu - (unsigned)c);
            best = best > key ? best : key;
        }
        red[(ty * TM + m) * 16 + tx] = best;
    }
    __syncthreads();

    if (tid < BM) {
        unsigned long long b = red[tid * 16];
        #pragma unroll
        for (int j = 1; j < 16; j++) {
            unsigned long long v = red[tid * 16 + j];
            b = b > v ? b : v;
        }
        atomicMax(&g_keys[row0 + tid], b);
    }
}

// ---------------------------------------------------------------------------
// Decode keys -> idx (as float) + gather z_q = emb[idx]
// ---------------------------------------------------------------------------
__global__ void gather_kernel(const float* __restrict__ emb,
                              float* __restrict__ zq_out,
                              float* __restrict__ idx_out) {
    int row = blockIdx.x;
    unsigned long long key = g_keys[row];
    unsigned int idx = 0xFFFFFFFFu - (unsigned int)(key & 0xFFFFFFFFull);
    if (threadIdx.x == 0) idx_out[row] = (float)idx;
    const float4* s = reinterpret_cast<const float4*>(emb + (size_t)idx * LATENT_DIM);
    float4* d = reinterpret_cast<float4*>(zq_out + (size_t)row * LATENT_DIM);
    d[threadIdx.x] = s[threadIdx.x];  // 64 threads x float4 = 256 floats
}

// ---------------------------------------------------------------------------
// Launch
// ---------------------------------------------------------------------------
extern "C" void kernel_launch(void* const* d_in, const int* in_sizes, int n_in,
                              void* d_out, int out_size) {
    const float* x     = (const float*)d_in[0];
    const float* enc_w = (const float*)d_in[1];
    const float* enc_b = (const float*)d_in[2];
    const float* emb   = (const float*)d_in[3];
    const float* dec_w = (const float*)d_in[4];
    const float* dec_b = (const float*)d_in[5];

    float* out     = (float*)d_out;
    float* x_recon = out;                                       // [B, 1024]
    float* z       = x_recon + (size_t)BATCH * INPUT_DIM;       // [B, 256]
    float* zq      = z + (size_t)BATCH * LATENT_DIM;            // [B, 256]
    float* idxf    = zq + (size_t)BATCH * LATENT_DIM;           // [B]

    // 0) codebook inv-norms + key reset
    init_kernel<<<(NUM_EMB + 255) / 256, 256>>>(emb);

    // 1) encoder: z = x @ enc_w^T + enc_b
    sgemm_abT_bias<<<dim3(LATENT_DIM / BN, BATCH / BM), NTHREADS>>>(
        x, enc_w, enc_b, z, BATCH, LATENT_DIM, INPUT_DIM);

    // 2) cosine-score GEMM + fused argmax
    sgemm_argmax<<<dim3(NUM_EMB / BN, BATCH / BM), NTHREADS>>>(
        z, emb, BATCH, NUM_EMB, LATENT_DIM);

    // 3) idx + z_q gather
    gather_kernel<<<BATCH, 64>>>(emb, zq, idxf);

    // 4) decoder: x_recon = z_q @ dec_w^T + dec_b   (dec_in == z_q in value)
    sgemm_abT_bias<<<dim3(INPUT_DIM / BN, BATCH / BM), NTHREADS>>>(
        zq, dec_w, dec_b, x_recon, BATCH, INPUT_DIM, LATENT_DIM);
}